// round 14
// baseline (speedup 1.0000x reference)
#include <cuda_runtime.h>
#include <cuda_fp16.h>
#include <math.h>

// ---------------- problem dims (fixed) ----------------
#define NN 50000
#define EE 600000
#define FIN 128
#define HID 128
#define KH 8
#define DA 16
#define DV 16
#define DM 64
#define NCLS 40
#define WO_IN  (HID + KH*DV)       // 256
#define QSW 480                    // GEMM N: q(128)|k(128)|v(128)|m(64)|gx(8)|gm(8)|pad(16)
#define QS32 288                   // fp32 store stride: q(128)|k(128)|gx(8)|pad(24)
#define VSH 256                    // fp16 store stride: v(128)|m(64)|gm(8)|pad
#define SLOPE 0.1f
#define NB 49                      // scan blocks: ceil(NN/1024)

// ---------------- device scratch (no allocations allowed) ----------------
__device__ float  g_h    [NN*HID];
__device__ float  g_h2   [NN*HID];
__device__ float  g_qkvm [(size_t)NN*QS32];
__device__ __half g_vh   [(size_t)NN*VSH];
__device__ float  g_wqkvm[HID*QSW];
__device__ float  g_woin [NN*WO_IN];
__device__ int    g_cnt   [NN];
__device__ int    g_rowptr[NN+1];
__device__ int    g_wptr  [NN];
__device__ int    g_esrc  [EE];
__device__ int    g_bsum  [64];
__device__ int    g_boff  [64];

// ---------------- f32x2 packed helpers ----------------
__device__ __forceinline__ unsigned long long fma2(unsigned long long a,
                                                   unsigned long long b,
                                                   unsigned long long c) {
    unsigned long long d;
    asm("fma.rn.f32x2 %0, %1, %2, %3;" : "=l"(d) : "l"(a), "l"(b), "l"(c));
    return d;
}
__device__ __forceinline__ unsigned long long dup2(float x) {
    unsigned long long d;
    asm("mov.b64 %0, {%1, %1};" : "=l"(d) : "f"(x));
    return d;
}
__device__ __forceinline__ void unpk2(unsigned long long d, float& lo, float& hi) {
    asm("mov.b64 {%0, %1}, %2;" : "=f"(lo), "=f"(hi) : "l"(d));
}

// ---------------- CSR build ----------------
__global__ void zero_cnt_k(int* cnt) {
    int i = blockIdx.x * blockDim.x + threadIdx.x;
    if (i < NN) cnt[i] = 0;
}
__global__ void hist_k(const int* __restrict__ dst, int* __restrict__ cnt) {
    int e = blockIdx.x * blockDim.x + threadIdx.x;
    if (e < EE) atomicAdd(&cnt[dst[e]], 1);
}
__global__ void scan_a_k(const int* __restrict__ cnt, int* __restrict__ rowptr,
                         int* __restrict__ bsum) {
    __shared__ int sh[1024];
    int t = threadIdx.x;
    int i = blockIdx.x * 1024 + t;
    int v = (i < NN) ? cnt[i] : 0;
    sh[t] = v; __syncthreads();
    #pragma unroll
    for (int off = 1; off < 1024; off <<= 1) {
        int u = (t >= off) ? sh[t - off] : 0;
        __syncthreads();
        sh[t] += u;
        __syncthreads();
    }
    if (i < NN) rowptr[i + 1] = sh[t];
    if (t == 1023) bsum[blockIdx.x] = sh[t];
}
__global__ void scan_b_k(const int* __restrict__ bsum, int* __restrict__ boff) {
    if (threadIdx.x == 0) {
        int run = 0;
        for (int b = 0; b < NB; b++) { boff[b] = run; run += bsum[b]; }
    }
}
__global__ void scan_c_k(const int* __restrict__ cnt, const int* __restrict__ boff,
                         int* __restrict__ rowptr, int* __restrict__ wptr) {
    int t = threadIdx.x;
    int i = blockIdx.x * 1024 + t;
    if (i == 0) rowptr[0] = 0;
    if (i < NN) {
        int e = rowptr[i + 1] + boff[blockIdx.x];
        rowptr[i + 1] = e;
        wptr[i] = e - cnt[i];
    }
}
__global__ void scatter_k(const int* __restrict__ src, const int* __restrict__ dst,
                          int* __restrict__ wptr, int* __restrict__ esrc) {
    int e = blockIdx.x * blockDim.x + threadIdx.x;
    if (e < EE) {
        int pos = atomicAdd(&wptr[dst[e]], 1);
        esrc[pos] = src[e];
    }
}

// pack layer weights [128 x 480] = [Wq | Wk | Wv | Wm | Wg_x | Wg_mean | 0pad]
__global__ void pack_qkvm_k(const float* __restrict__ Wq, const float* __restrict__ Wk,
                            const float* __restrict__ Wv, const float* __restrict__ Wm,
                            const float* __restrict__ Wg, float* __restrict__ Bf) {
    int idx = blockIdx.x * blockDim.x + threadIdx.x;
    if (idx >= HID*QSW) return;
    int r = idx / QSW, c = idx % QSW;
    float v;
    if      (c < 128) v = Wq[r*128 + c];
    else if (c < 256) v = Wk[r*128 + (c-128)];
    else if (c < 384) v = Wv[r*128 + (c-256)];
    else if (c < 448) v = Wm[r*64  + (c-384)];
    else if (c < 456) v = Wg[r*KH + (c-448)];            // x rows of Wg
    else if (c < 464) v = Wg[(192 + r)*KH + (c-456)];    // mean rows of Wg
    else              v = 0.f;                           // pad
    Bf[idx] = v;
}

// ---------------- 128x128x16 SGEMM, 8x8 microtile, f32x2 -----------------
// A stored DUPLICATED in smem: As2[k][2m]=As2[k][2m+1]=a -> lds.64 gives (a,a)
// pair directly, eliminating per-k dup2 MOVs (issue mix 44 -> 38 per k-step).
// Requires: Kc % 16 == 0, Nc % 4 == 0.
__global__ __launch_bounds__(256, 2)
void sgemm128_k(const float* __restrict__ A, const float* __restrict__ B,
                float* __restrict__ C, __half* __restrict__ vh,
                int M, int Nc, int Kc, int act) {
    __shared__ float As2[2][16][256];   // 32 KB
    __shared__ float Bs[2][16][128];    // 16 KB (total = 48 KB static limit)
    int tid = threadIdx.x;
    int tx = tid & 15, ty = tid >> 4;
    int rowBase = blockIdx.y * 128;
    int colBase = blockIdx.x * 128;

    int arow  = tid >> 1;
    int acol4 = (tid & 1) * 4;
    int brow  = tid >> 5;
    int bcol4 = (tid & 31) * 4;
    int agr = rowBase + arow;
    int bgc = colBase + bcol4;

    float4 pa[2], pb[2];

    #pragma unroll
    for (int half = 0; half < 2; half++) {
        int ac = acol4 + half * 8;
        pa[half] = make_float4(0.f, 0.f, 0.f, 0.f);
        if (agr < M) pa[half] = *(const float4*)(A + (size_t)agr*Kc + ac);
        pb[half] = make_float4(0.f, 0.f, 0.f, 0.f);
        if (bgc < Nc) pb[half] = *(const float4*)(B + (size_t)(brow + half*8)*Nc + bgc);
    }
    #pragma unroll
    for (int half = 0; half < 2; half++) {
        int ac = acol4 + half * 8;
        *(unsigned long long*)&As2[0][ac+0][2*arow] = dup2(pa[half].x);
        *(unsigned long long*)&As2[0][ac+1][2*arow] = dup2(pa[half].y);
        *(unsigned long long*)&As2[0][ac+2][2*arow] = dup2(pa[half].z);
        *(unsigned long long*)&As2[0][ac+3][2*arow] = dup2(pa[half].w);
        *(float4*)&Bs[0][brow + half*8][bcol4] = pb[half];
    }
    __syncthreads();

    unsigned long long acc2[8][4];
    #pragma unroll
    for (int i = 0; i < 8; i++)
        #pragma unroll
        for (int j = 0; j < 4; j++) acc2[i][j] = 0ull;

    int nchunks = Kc >> 4;
    for (int c = 0; c < nchunks; c++) {
        int cur = c & 1;
        if (c + 1 < nchunks) {
            int k0 = (c + 1) << 4;
            #pragma unroll
            for (int half = 0; half < 2; half++) {
                int ac = acol4 + half * 8;
                pa[half] = make_float4(0.f, 0.f, 0.f, 0.f);
                if (agr < M) pa[half] = *(const float4*)(A + (size_t)agr*Kc + k0 + ac);
                pb[half] = make_float4(0.f, 0.f, 0.f, 0.f);
                if (bgc < Nc) pb[half] = *(const float4*)(B + (size_t)(k0 + brow + half*8)*Nc + bgc);
            }
        }
        #pragma unroll
        for (int kk = 0; kk < 16; kk++) {
            const unsigned long long* ap0 = (const unsigned long long*)&As2[cur][kk][ty*8];
            const unsigned long long* ap1 = (const unsigned long long*)&As2[cur][kk][128 + ty*8];
            const unsigned long long* bp0 = (const unsigned long long*)&Bs[cur][kk][tx*4];
            const unsigned long long* bp1 = (const unsigned long long*)&Bs[cur][kk][64 + tx*4];
            unsigned long long b2[4] = {bp0[0], bp0[1], bp1[0], bp1[1]};
            unsigned long long a2[8] = {ap0[0], ap0[1], ap0[2], ap0[3],
                                        ap1[0], ap1[1], ap1[2], ap1[3]};
            #pragma unroll
            for (int i = 0; i < 8; i++) {
                acc2[i][0] = fma2(a2[i], b2[0], acc2[i][0]);
                acc2[i][1] = fma2(a2[i], b2[1], acc2[i][1]);
                acc2[i][2] = fma2(a2[i], b2[2], acc2[i][2]);
                acc2[i][3] = fma2(a2[i], b2[3], acc2[i][3]);
            }
        }
        if (c + 1 < nchunks) {
            int nxt = cur ^ 1;
            #pragma unroll
            for (int half = 0; half < 2; half++) {
                int ac = acol4 + half * 8;
                *(unsigned long long*)&As2[nxt][ac+0][2*arow] = dup2(pa[half].x);
                *(unsigned long long*)&As2[nxt][ac+1][2*arow] = dup2(pa[half].y);
                *(unsigned long long*)&As2[nxt][ac+2][2*arow] = dup2(pa[half].z);
                *(unsigned long long*)&As2[nxt][ac+3][2*arow] = dup2(pa[half].w);
                *(float4*)&Bs[nxt][brow + half*8][bcol4] = pb[half];
            }
        }
        __syncthreads();
    }

    #pragma unroll
    for (int ih = 0; ih < 2; ih++) {
        #pragma unroll
        for (int i = 0; i < 4; i++) {
            int gr = rowBase + ih*64 + ty*4 + i;
            if (gr >= M) continue;
            #pragma unroll
            for (int jh = 0; jh < 2; jh++) {
                int gc = colBase + jh*64 + tx*4;
                if (gc >= Nc) continue;
                float4 vv;
                unpk2(acc2[ih*4+i][jh*2+0], vv.x, vv.y);
                unpk2(acc2[ih*4+i][jh*2+1], vv.z, vv.w);
                if (vh == nullptr) {
                    if (act == 1) {
                        vv.x = vv.x > 0.f ? vv.x : SLOPE*vv.x;
                        vv.y = vv.y > 0.f ? vv.y : SLOPE*vv.y;
                        vv.z = vv.z > 0.f ? vv.z : SLOPE*vv.z;
                        vv.w = vv.w > 0.f ? vv.w : SLOPE*vv.w;
                    }
                    *(float4*)(C + (size_t)gr*Nc + gc) = vv;
                } else {
                    if (gc < 256) {
                        *(float4*)(C + (size_t)gr*QS32 + gc) = vv;
                    } else if (gc >= 448 && gc < 456) {
                        *(float4*)(C + (size_t)gr*QS32 + 256 + (gc - 448)) = vv;
                    }
                    if (gc >= 256 && gc < 464 && !(gc >= 448 && gc < 456)) {
                        int hidx;
                        if      (gc < 384) hidx = gc - 256;          // v: 0..127
                        else if (gc < 448) hidx = 128 + (gc - 384);  // m: 128..191
                        else               hidx = 192 + (gc - 456);  // gm: 192..199
                        __half2 h0 = __floats2half2_rn(vv.x, vv.y);
                        __half2 h1 = __floats2half2_rn(vv.z, vv.w);
                        uint2 pk;
                        pk.x = *(unsigned int*)&h0;
                        pk.y = *(unsigned int*)&h1;
                        *(uint2*)(vh + (size_t)gr*VSH + hidx) = pk;
                    }
                }
            }
        }
    }
}

// ---------------- fused node kernel: attn+pool+gate+woin ----------------
__global__ __launch_bounds__(256)
void node_fused_k(const float* __restrict__ qkvm, const __half* __restrict__ vh,
                  const float* __restrict__ h,
                  const int* __restrict__ rowptr, const int* __restrict__ esrc,
                  const float* __restrict__ Wg, float* __restrict__ woin) {
    __shared__ float Ws[DM][KH+1];
    int tid = threadIdx.x;                // 256
    for (int i = tid; i < DM*KH; i += 256) Ws[i/KH][i%KH] = Wg[(128 + i/KH)*KH + (i%KH)];
    __syncthreads();

    int warp = tid >> 5, lane = tid & 31;
    int n = blockIdx.x * 8 + warp;
    if (n >= NN) return;
    int head = lane >> 2;

    float4 q4 = *(const float4*)(qkvm + (size_t)n*QS32 + lane*4);   // q
    int start = rowptr[n], end = rowptr[n+1];
    int cnt = end - start;

    float smx = -INFINITY, denom = 0.f;
    float4 acc = make_float4(0.f, 0.f, 0.f, 0.f);
    float mx0 = -INFINITY, mx1 = -INFINITY;
    float gmsum = 0.f;

    for (int i = start; i < end; i++) {
        int s = esrc[i];
        const float* kb = qkvm + (size_t)s*QS32 + 128;
        float4 k4 = *(const float4*)(kb + lane*4);
        float p = q4.x*k4.x + q4.y*k4.y + q4.z*k4.z + q4.w*k4.w;
        p += __shfl_xor_sync(0xffffffffu, p, 1);
        p += __shfl_xor_sync(0xffffffffu, p, 2);
        float nm = fmaxf(smx, p);
        float sc = __expf(smx - nm), ex = __expf(p - nm);
        denom = denom*sc + ex;
        const __half* vb = vh + (size_t)s*VSH;
        uint2 raw = *(const uint2*)(vb + lane*4);
        float2 va = __half22float2(*(__half2*)&raw.x);
        float2 vbp = __half22float2(*(__half2*)&raw.y);
        acc.x = acc.x*sc + ex*va.x;
        acc.y = acc.y*sc + ex*va.y;
        acc.z = acc.z*sc + ex*vbp.x;
        acc.w = acc.w*sc + ex*vbp.y;
        smx = nm;
        mx0 = fmaxf(mx0, __half2float(vb[128 + lane]));
        mx1 = fmaxf(mx1, __half2float(vb[160 + lane]));
        gmsum += __half2float(vb[192 + head]);
    }

    float inv = 1.f / (denom + 1e-16f);
    float4 o = make_float4(acc.x*inv, acc.y*inv, acc.z*inv, acc.w*inv);  // agg

    float mp0 = cnt ? mx0 : 0.f, mp1 = cnt ? mx1 : 0.f;
    float invd = 1.f / fmaxf((float)cnt, 1.f);

    float ga[KH] = {};
    #pragma unroll
    for (int oo = 0; oo < KH; oo++)
        ga[oo] = mp0 * Ws[lane][oo] + mp1 * Ws[lane + 32][oo];
    #pragma unroll
    for (int oo = 0; oo < KH; oo++)
        #pragma unroll
        for (int off = 16; off; off >>= 1)
            ga[oo] += __shfl_xor_sync(0xffffffffu, ga[oo], off);

    float gsum = ga[0];
    #pragma unroll
    for (int oo = 1; oo < KH; oo++) if (head == oo) gsum = ga[oo];
    gsum += qkvm[(size_t)n*QS32 + 256 + head];   // x part of gate (fp32)
    gsum += gmsum * invd;                        // mean part of gate
    float gh = 1.f / (1.f + expf(-gsum));

    const float* hn = h + (size_t)n*HID;
    float* w = woin + (size_t)n*WO_IN;
    *(float4*)(w + lane*4) = *(const float4*)(hn + lane*4);
    *(float4*)(w + 128 + lane*4) = make_float4(gh*o.x, gh*o.y, gh*o.z, gh*o.w);
}

// ---------------- fused logits + log_softmax: block-tiled GEMM ----------------
__global__ __launch_bounds__(256)
void logits_lsm2_k(const float* __restrict__ h, const float* __restrict__ w_out,
                   float* __restrict__ out) {
    __shared__ float Ws[HID][48];
    __shared__ float HsT[HID][33];
    int tid = threadIdx.x;               // 256
    int n0 = blockIdx.x * 32;

    for (int i = tid; i < HID*48; i += 256) {
        int r = i / 48, c = i % 48;
        Ws[r][c] = (c < NCLS) ? w_out[r*NCLS + c] : 0.f;
    }
    for (int idx = tid; idx < 32*32; idx += 256) {
        int r = idx >> 5, c4 = (idx & 31) * 4;
        int n = n0 + r;
        float4 hv = *(const float4*)(h + (size_t)((n < NN) ? n : 0)*HID + c4);
        HsT[c4+0][r] = hv.x;
        HsT[c4+1][r] = hv.y;
        HsT[c4+2][r] = hv.z;
        HsT[c4+3][r] = hv.w;
    }
    __syncthreads();

    int tx = tid & 15, ty = tid >> 4;
    float acc[2][3] = {};
    #pragma unroll 4
    for (int kk = 0; kk < HID; kk++) {
        float a0 = HsT[kk][ty*2 + 0];
        float a1 = HsT[kk][ty*2 + 1];
        float b0 = Ws[kk][tx*3 + 0];
        float b1 = Ws[kk][tx*3 + 1];
        float b2 = Ws[kk][tx*3 + 2];
        acc[0][0] += a0*b0; acc[0][1] += a0*b1; acc[0][2] += a0*b2;
        acc[1][0] += a1*b0; acc[1][1] += a1*b1; acc[1][2] += a1*b2;
    }
    __syncthreads();

    float* Ls = &HsT[0][0];
    #pragma unroll
    for (int i = 0; i < 2; i++)
        #pragma unroll
        for (int j = 0; j < 3; j++)
            Ls[(ty*2 + i)*48 + tx*3 + j] = acc[i][j];
    __syncthreads();

    int warp = tid >> 5, lane = tid & 31;
    #pragma unroll
    for (int rr = 0; rr < 4; rr++) {
        int r = warp*4 + rr;
        int n = n0 + r;
        if (n >= NN) continue;
        float v0 = Ls[r*48 + lane];
        float v1 = (lane < NCLS - 32) ? Ls[r*48 + 32 + lane] : -INFINITY;
        float mx = fmaxf(v0, v1);
        #pragma unroll
        for (int off = 16; off > 0; off >>= 1)
            mx = fmaxf(mx, __shfl_xor_sync(0xffffffffu, mx, off));
        float sm = expf(v0 - mx) + ((lane < NCLS - 32) ? expf(v1 - mx) : 0.f);
        #pragma unroll
        for (int off = 16; off > 0; off >>= 1)
            sm += __shfl_xor_sync(0xffffffffu, sm, off);
        float lse = mx + logf(sm);
        out[(size_t)n*NCLS + lane] = v0 - lse;
        if (lane < NCLS - 32) out[(size_t)n*NCLS + 32 + lane] = v1 - lse;
    }
}

// ---------------- host side ----------------
static inline void launch_gemm(const float* A, const float* B, float* C,
                               __half* vh, int M, int Nc, int Kc, int act) {
    dim3 grid((Nc + 127) / 128, (M + 127) / 128);
    sgemm128_k<<<grid, 256>>>(A, B, C, vh, M, Nc, Kc, act);
}

extern "C" void kernel_launch(void* const* d_in, const int* in_sizes, int n_in,
                              void* d_out, int out_size) {
    const float* x     = (const float*)d_in[0];
    const int*   ei    = (const int*)d_in[1];      // int32 (JAX demotes int64)
    const float* w_in  = (const float*)d_in[2];
    const float* w_out = (const float*)d_in[3];
    const float* Wq    = (const float*)d_in[4];
    const float* Wk    = (const float*)d_in[5];
    const float* Wv    = (const float*)d_in[6];
    const float* Wm    = (const float*)d_in[7];
    const float* Wg    = (const float*)d_in[8];
    const float* Wo    = (const float*)d_in[9];
    float* out = (float*)d_out;

    const int* srcA = ei;
    const int* dstA = ei + EE;

    float *h, *h2, *qkvm, *wqkvm, *woin;
    __half* vh;
    int *cnt, *rowptr, *wptr, *esrc, *bsum, *boff;
    cudaGetSymbolAddress((void**)&h,      g_h);
    cudaGetSymbolAddress((void**)&h2,     g_h2);
    cudaGetSymbolAddress((void**)&qkvm,   g_qkvm);
    cudaGetSymbolAddress((void**)&vh,     g_vh);
    cudaGetSymbolAddress((void**)&wqkvm,  g_wqkvm);
    cudaGetSymbolAddress((void**)&woin,   g_woin);
    cudaGetSymbolAddress((void**)&cnt,    g_cnt);
    cudaGetSymbolAddress((void**)&rowptr, g_rowptr);
    cudaGetSymbolAddress((void**)&wptr,   g_wptr);
    cudaGetSymbolAddress((void**)&esrc,   g_esrc);
    cudaGetSymbolAddress((void**)&bsum,   g_bsum);
    cudaGetSymbolAddress((void**)&boff,   g_boff);

    // ---- CSR build (once per call, reused across layers) ----
    zero_cnt_k<<<(NN + 255) / 256, 256>>>(cnt);
    hist_k<<<(EE + 255) / 256, 256>>>(dstA, cnt);
    scan_a_k<<<NB, 1024>>>(cnt, rowptr, bsum);
    scan_b_k<<<1, 32>>>(bsum, boff);
    scan_c_k<<<NB, 1024>>>(cnt, boff, rowptr, wptr);
    scatter_k<<<(EE + 255) / 256, 256>>>(srcA, dstA, wptr, esrc);

    // h = x @ weight_in
    launch_gemm(x, w_in, h, nullptr, NN, HID, FIN, 0);

    float* hcur = h;
    float* hnext = h2;

    for (int layer = 0; layer < 2; layer++) {
        const float* wq = Wq + (size_t)layer * HID * (KH*DA);
        const float* wk = Wk + (size_t)layer * HID * (KH*DA);
        const float* wv = Wv + (size_t)layer * HID * (KH*DV);
        const float* wm = Wm + (size_t)layer * HID * DM;
        const float* wg = Wg + (size_t)layer * 320 * KH;
        const float* wo = Wo + (size_t)layer * WO_IN * HID;

        pack_qkvm_k<<<(HID*QSW + 255) / 256, 256>>>(wq, wk, wv, wm, wg, wqkvm);
        launch_gemm(hcur, wqkvm, qkvm, vh, NN, QSW, HID, 0);  // split fp32/fp16 stores

        node_fused_k<<<(NN + 7) / 8, 256>>>(qkvm, vh, hcur, rowptr, esrc, wg, woin);

        launch_gemm(woin, wo, hnext, nullptr, NN, HID, WO_IN, 1);  // leaky_relu

        float* t = hcur; hcur = hnext; hnext = t;
    }

    // fused logits + log_softmax (block-tiled)
    logits_lsm2_k<<<(NN + 31) / 32, 256>>>(hcur, w_out, out);
}

// round 15
// speedup vs baseline: 1.1173x; 1.1173x over previous
#include <cuda_runtime.h>
#include <cuda_fp16.h>
#include <math.h>

// ---------------- problem dims (fixed) ----------------
#define NN 50000
#define EE 600000
#define FIN 128
#define HID 128
#define KH 8
#define DA 16
#define DV 16
#define DM 64
#define NCLS 40
#define WO_IN  (HID + KH*DV)       // 256
#define QSW 480                    // GEMM N: q(128)|k(128)|v(128)|m(64)|gx(8)|gm(8)|pad(16)
#define QS32 288                   // fp32 store stride: q(128)|k(128)|gx(8)|pad(24)
#define VSH 256                    // fp16 store stride: v(128)|m(64)|gm(8)|pad
#define SLOPE 0.1f
#define NB 49                      // scan blocks: ceil(NN/1024)

// ---------------- device scratch (no allocations allowed) ----------------
__device__ float  g_h    [NN*HID];
__device__ float  g_h2   [NN*HID];
__device__ float  g_qkvm [(size_t)NN*QS32];
__device__ __half g_vh   [(size_t)NN*VSH];
__device__ float  g_wqkvm[HID*QSW];
__device__ float  g_gagg [NN*HID];
__device__ int    g_cnt   [NN];
__device__ int    g_rowptr[NN+1];
__device__ int    g_wptr  [NN];
__device__ int    g_esrc  [EE];
__device__ int    g_bsum  [64];
__device__ int    g_boff  [64];

// ---------------- f32x2 packed helpers ----------------
__device__ __forceinline__ unsigned long long fma2(unsigned long long a,
                                                   unsigned long long b,
                                                   unsigned long long c) {
    unsigned long long d;
    asm("fma.rn.f32x2 %0, %1, %2, %3;" : "=l"(d) : "l"(a), "l"(b), "l"(c));
    return d;
}
__device__ __forceinline__ unsigned long long dup2(float x) {
    unsigned long long d;
    asm("mov.b64 %0, {%1, %1};" : "=l"(d) : "f"(x));
    return d;
}
__device__ __forceinline__ void unpk2(unsigned long long d, float& lo, float& hi) {
    asm("mov.b64 {%0, %1}, %2;" : "=f"(lo), "=f"(hi) : "l"(d));
}

// ---------------- CSR build ----------------
__global__ void zero_cnt_k(int* cnt) {
    int i = blockIdx.x * blockDim.x + threadIdx.x;
    if (i < NN) cnt[i] = 0;
}
__global__ void hist_k(const int* __restrict__ dst, int* __restrict__ cnt) {
    int e = blockIdx.x * blockDim.x + threadIdx.x;
    if (e < EE) atomicAdd(&cnt[dst[e]], 1);
}
__global__ void scan_a_k(const int* __restrict__ cnt, int* __restrict__ rowptr,
                         int* __restrict__ bsum) {
    __shared__ int sh[1024];
    int t = threadIdx.x;
    int i = blockIdx.x * 1024 + t;
    int v = (i < NN) ? cnt[i] : 0;
    sh[t] = v; __syncthreads();
    #pragma unroll
    for (int off = 1; off < 1024; off <<= 1) {
        int u = (t >= off) ? sh[t - off] : 0;
        __syncthreads();
        sh[t] += u;
        __syncthreads();
    }
    if (i < NN) rowptr[i + 1] = sh[t];
    if (t == 1023) bsum[blockIdx.x] = sh[t];
}
__global__ void scan_b_k(const int* __restrict__ bsum, int* __restrict__ boff) {
    if (threadIdx.x == 0) {
        int run = 0;
        for (int b = 0; b < NB; b++) { boff[b] = run; run += bsum[b]; }
    }
}
__global__ void scan_c_k(const int* __restrict__ cnt, const int* __restrict__ boff,
                         int* __restrict__ rowptr, int* __restrict__ wptr) {
    int t = threadIdx.x;
    int i = blockIdx.x * 1024 + t;
    if (i == 0) rowptr[0] = 0;
    if (i < NN) {
        int e = rowptr[i + 1] + boff[blockIdx.x];
        rowptr[i + 1] = e;
        wptr[i] = e - cnt[i];
    }
}
__global__ void scatter_k(const int* __restrict__ src, const int* __restrict__ dst,
                          int* __restrict__ wptr, int* __restrict__ esrc) {
    int e = blockIdx.x * blockDim.x + threadIdx.x;
    if (e < EE) {
        int pos = atomicAdd(&wptr[dst[e]], 1);
        esrc[pos] = src[e];
    }
}

// pack layer weights [128 x 480] = [Wq | Wk | Wv | Wm | Wg_x | Wg_mean | 0pad]
__global__ void pack_qkvm_k(const float* __restrict__ Wq, const float* __restrict__ Wk,
                            const float* __restrict__ Wv, const float* __restrict__ Wm,
                            const float* __restrict__ Wg, float* __restrict__ Bf) {
    int idx = blockIdx.x * blockDim.x + threadIdx.x;
    if (idx >= HID*QSW) return;
    int r = idx / QSW, c = idx % QSW;
    float v;
    if      (c < 128) v = Wq[r*128 + c];
    else if (c < 256) v = Wk[r*128 + (c-128)];
    else if (c < 384) v = Wv[r*128 + (c-256)];
    else if (c < 448) v = Wm[r*64  + (c-384)];
    else if (c < 456) v = Wg[r*KH + (c-448)];            // x rows of Wg
    else if (c < 464) v = Wg[(192 + r)*KH + (c-456)];    // mean rows of Wg
    else              v = 0.f;                           // pad
    Bf[idx] = v;
}

// ---------------- 128x128x16 SGEMM, 8x8 microtile, f32x2, double-buffered ----
// Requires: Kc % 16 == 0, Nc % 4 == 0.
// A2 != null: split-A mode, Kc must be 256; K-rows 0..127 from A (stride 128),
//             128..255 from A2 (stride 128). 128-boundary is chunk-aligned.
// vh == null: plain C[M,Nc] store (+ optional leaky_relu when act==1).
// vh != null: qkvm mode (Nc=480): fp32 q|k|gx -> C stride QS32; fp16 v|m|gm -> vh.
__global__ __launch_bounds__(256, 2)
void sgemm128_k(const float* __restrict__ A, const float* __restrict__ A2,
                const float* __restrict__ B,
                float* __restrict__ C, __half* __restrict__ vh,
                int M, int Nc, int Kc, int act) {
    __shared__ float As[2][16][128];
    __shared__ float Bs[2][16][128];
    int tid = threadIdx.x;
    int tx = tid & 15, ty = tid >> 4;
    int rowBase = blockIdx.y * 128;
    int colBase = blockIdx.x * 128;

    int arow  = tid >> 1;
    int acol4 = (tid & 1) * 4;
    int brow  = tid >> 5;
    int bcol4 = (tid & 31) * 4;
    int agr = rowBase + arow;
    int bgc = colBase + bcol4;
    int KcA = A2 ? 128 : Kc;     // row stride of A when split

    float4 pa[2], pb[2];

    #pragma unroll
    for (int half = 0; half < 2; half++) {
        int ac = acol4 + half * 8;
        pa[half] = make_float4(0.f, 0.f, 0.f, 0.f);
        if (agr < M) pa[half] = *(const float4*)(A + (size_t)agr*KcA + ac);
        pb[half] = make_float4(0.f, 0.f, 0.f, 0.f);
        if (bgc < Nc) pb[half] = *(const float4*)(B + (size_t)(brow + half*8)*Nc + bgc);
    }
    #pragma unroll
    for (int half = 0; half < 2; half++) {
        int ac = acol4 + half * 8;
        As[0][ac+0][arow] = pa[half].x;
        As[0][ac+1][arow] = pa[half].y;
        As[0][ac+2][arow] = pa[half].z;
        As[0][ac+3][arow] = pa[half].w;
        *(float4*)&Bs[0][brow + half*8][bcol4] = pb[half];
    }
    __syncthreads();

    unsigned long long acc2[8][4];
    #pragma unroll
    for (int i = 0; i < 8; i++)
        #pragma unroll
        for (int j = 0; j < 4; j++) acc2[i][j] = 0ull;

    int nchunks = Kc >> 4;
    for (int c = 0; c < nchunks; c++) {
        int cur = c & 1;
        if (c + 1 < nchunks) {
            int k0 = (c + 1) << 4;
            const float* Ap = A;
            int kk0 = k0;
            if (A2 && k0 >= 128) { Ap = A2; kk0 = k0 - 128; }
            #pragma unroll
            for (int half = 0; half < 2; half++) {
                int ac = acol4 + half * 8;
                pa[half] = make_float4(0.f, 0.f, 0.f, 0.f);
                if (agr < M) pa[half] = *(const float4*)(Ap + (size_t)agr*KcA + kk0 + ac);
                pb[half] = make_float4(0.f, 0.f, 0.f, 0.f);
                if (bgc < Nc) pb[half] = *(const float4*)(B + (size_t)(k0 + brow + half*8)*Nc + bgc);
            }
        }
        #pragma unroll
        for (int kk = 0; kk < 16; kk++) {
            float4 a0 = *(const float4*)&As[cur][kk][ty*4];
            float4 a1 = *(const float4*)&As[cur][kk][64 + ty*4];
            const unsigned long long* bp0 = (const unsigned long long*)&Bs[cur][kk][tx*4];
            const unsigned long long* bp1 = (const unsigned long long*)&Bs[cur][kk][64 + tx*4];
            unsigned long long b2[4] = {bp0[0], bp0[1], bp1[0], bp1[1]};
            float a[8] = {a0.x,a0.y,a0.z,a0.w, a1.x,a1.y,a1.z,a1.w};
            #pragma unroll
            for (int i = 0; i < 8; i++) {
                unsigned long long ad = dup2(a[i]);
                acc2[i][0] = fma2(ad, b2[0], acc2[i][0]);
                acc2[i][1] = fma2(ad, b2[1], acc2[i][1]);
                acc2[i][2] = fma2(ad, b2[2], acc2[i][2]);
                acc2[i][3] = fma2(ad, b2[3], acc2[i][3]);
            }
        }
        if (c + 1 < nchunks) {
            int nxt = cur ^ 1;
            #pragma unroll
            for (int half = 0; half < 2; half++) {
                int ac = acol4 + half * 8;
                As[nxt][ac+0][arow] = pa[half].x;
                As[nxt][ac+1][arow] = pa[half].y;
                As[nxt][ac+2][arow] = pa[half].z;
                As[nxt][ac+3][arow] = pa[half].w;
                *(float4*)&Bs[nxt][brow + half*8][bcol4] = pb[half];
            }
        }
        __syncthreads();
    }

    #pragma unroll
    for (int ih = 0; ih < 2; ih++) {
        #pragma unroll
        for (int i = 0; i < 4; i++) {
            int gr = rowBase + ih*64 + ty*4 + i;
            if (gr >= M) continue;
            #pragma unroll
            for (int jh = 0; jh < 2; jh++) {
                int gc = colBase + jh*64 + tx*4;
                if (gc >= Nc) continue;
                float4 vv;
                unpk2(acc2[ih*4+i][jh*2+0], vv.x, vv.y);
                unpk2(acc2[ih*4+i][jh*2+1], vv.z, vv.w);
                if (vh == nullptr) {
                    if (act == 1) {
                        vv.x = vv.x > 0.f ? vv.x : SLOPE*vv.x;
                        vv.y = vv.y > 0.f ? vv.y : SLOPE*vv.y;
                        vv.z = vv.z > 0.f ? vv.z : SLOPE*vv.z;
                        vv.w = vv.w > 0.f ? vv.w : SLOPE*vv.w;
                    }
                    *(float4*)(C + (size_t)gr*Nc + gc) = vv;
                } else {
                    if (gc < 256) {
                        *(float4*)(C + (size_t)gr*QS32 + gc) = vv;
                    } else if (gc >= 448 && gc < 456) {
                        *(float4*)(C + (size_t)gr*QS32 + 256 + (gc - 448)) = vv;
                    }
                    if (gc >= 256 && gc < 464 && !(gc >= 448 && gc < 456)) {
                        int hidx;
                        if      (gc < 384) hidx = gc - 256;          // v: 0..127
                        else if (gc < 448) hidx = 128 + (gc - 384);  // m: 128..191
                        else               hidx = 192 + (gc - 456);  // gm: 192..199
                        __half2 h0 = __floats2half2_rn(vv.x, vv.y);
                        __half2 h1 = __floats2half2_rn(vv.z, vv.w);
                        uint2 pk;
                        pk.x = *(unsigned int*)&h0;
                        pk.y = *(unsigned int*)&h1;
                        *(uint2*)(vh + (size_t)gr*VSH + hidx) = pk;
                    }
                }
            }
        }
    }
}

// ---------------- fused node kernel: attn+pool+gate -> gagg ----------------
// warp per node; online softmax; writes only gagg[n] = gate*agg (128 floats).
__global__ __launch_bounds__(256)
void node_fused_k(const float* __restrict__ qkvm, const __half* __restrict__ vh,
                  const int* __restrict__ rowptr, const int* __restrict__ esrc,
                  const float* __restrict__ Wg, float* __restrict__ gagg) {
    __shared__ float Ws[DM][KH+1];
    int tid = threadIdx.x;                // 256
    for (int i = tid; i < DM*KH; i += 256) Ws[i/KH][i%KH] = Wg[(128 + i/KH)*KH + (i%KH)];
    __syncthreads();

    int warp = tid >> 5, lane = tid & 31;
    int n = blockIdx.x * 8 + warp;
    if (n >= NN) return;
    int head = lane >> 2;

    float4 q4 = *(const float4*)(qkvm + (size_t)n*QS32 + lane*4);   // q
    int start = rowptr[n], end = rowptr[n+1];
    int cnt = end - start;

    float smx = -INFINITY, denom = 0.f;
    float4 acc = make_float4(0.f, 0.f, 0.f, 0.f);
    float mx0 = -INFINITY, mx1 = -INFINITY;
    float gmsum = 0.f;

    for (int i = start; i < end; i++) {
        int s = esrc[i];
        const float* kb = qkvm + (size_t)s*QS32 + 128;
        float4 k4 = *(const float4*)(kb + lane*4);
        float p = q4.x*k4.x + q4.y*k4.y + q4.z*k4.z + q4.w*k4.w;
        p += __shfl_xor_sync(0xffffffffu, p, 1);
        p += __shfl_xor_sync(0xffffffffu, p, 2);
        float nm = fmaxf(smx, p);
        float sc = __expf(smx - nm), ex = __expf(p - nm);
        denom = denom*sc + ex;
        const __half* vb = vh + (size_t)s*VSH;
        uint2 raw = *(const uint2*)(vb + lane*4);
        float2 va = __half22float2(*(__half2*)&raw.x);
        float2 vbp = __half22float2(*(__half2*)&raw.y);
        acc.x = acc.x*sc + ex*va.x;
        acc.y = acc.y*sc + ex*va.y;
        acc.z = acc.z*sc + ex*vbp.x;
        acc.w = acc.w*sc + ex*vbp.y;
        smx = nm;
        mx0 = fmaxf(mx0, __half2float(vb[128 + lane]));
        mx1 = fmaxf(mx1, __half2float(vb[160 + lane]));
        gmsum += __half2float(vb[192 + head]);
    }

    float inv = 1.f / (denom + 1e-16f);
    float4 o = make_float4(acc.x*inv, acc.y*inv, acc.z*inv, acc.w*inv);  // agg

    float mp0 = cnt ? mx0 : 0.f, mp1 = cnt ? mx1 : 0.f;
    float invd = 1.f / fmaxf((float)cnt, 1.f);

    float ga[KH] = {};
    #pragma unroll
    for (int oo = 0; oo < KH; oo++)
        ga[oo] = mp0 * Ws[lane][oo] + mp1 * Ws[lane + 32][oo];
    #pragma unroll
    for (int oo = 0; oo < KH; oo++)
        #pragma unroll
        for (int off = 16; off; off >>= 1)
            ga[oo] += __shfl_xor_sync(0xffffffffu, ga[oo], off);

    float gsum = ga[0];
    #pragma unroll
    for (int oo = 1; oo < KH; oo++) if (head == oo) gsum = ga[oo];
    gsum += qkvm[(size_t)n*QS32 + 256 + head];   // x part of gate (fp32)
    gsum += gmsum * invd;                        // mean part of gate
    float gh = 1.f / (1.f + expf(-gsum));

    *(float4*)(gagg + (size_t)n*HID + lane*4) =
        make_float4(gh*o.x, gh*o.y, gh*o.z, gh*o.w);
}

// ---------------- fused logits + log_softmax: block-tiled GEMM ----------------
__global__ __launch_bounds__(256)
void logits_lsm2_k(const float* __restrict__ h, const float* __restrict__ w_out,
                   float* __restrict__ out) {
    __shared__ float Ws[HID][48];
    __shared__ float HsT[HID][33];
    int tid = threadIdx.x;               // 256
    int n0 = blockIdx.x * 32;

    for (int i = tid; i < HID*48; i += 256) {
        int r = i / 48, c = i % 48;
        Ws[r][c] = (c < NCLS) ? w_out[r*NCLS + c] : 0.f;
    }
    for (int idx = tid; idx < 32*32; idx += 256) {
        int r = idx >> 5, c4 = (idx & 31) * 4;
        int n = n0 + r;
        float4 hv = *(const float4*)(h + (size_t)((n < NN) ? n : 0)*HID + c4);
        HsT[c4+0][r] = hv.x;
        HsT[c4+1][r] = hv.y;
        HsT[c4+2][r] = hv.z;
        HsT[c4+3][r] = hv.w;
    }
    __syncthreads();

    int tx = tid & 15, ty = tid >> 4;
    float acc[2][3] = {};
    #pragma unroll 4
    for (int kk = 0; kk < HID; kk++) {
        float a0 = HsT[kk][ty*2 + 0];
        float a1 = HsT[kk][ty*2 + 1];
        float b0 = Ws[kk][tx*3 + 0];
        float b1 = Ws[kk][tx*3 + 1];
        float b2 = Ws[kk][tx*3 + 2];
        acc[0][0] += a0*b0; acc[0][1] += a0*b1; acc[0][2] += a0*b2;
        acc[1][0] += a1*b0; acc[1][1] += a1*b1; acc[1][2] += a1*b2;
    }
    __syncthreads();

    float* Ls = &HsT[0][0];
    #pragma unroll
    for (int i = 0; i < 2; i++)
        #pragma unroll
        for (int j = 0; j < 3; j++)
            Ls[(ty*2 + i)*48 + tx*3 + j] = acc[i][j];
    __syncthreads();

    int warp = tid >> 5, lane = tid & 31;
    #pragma unroll
    for (int rr = 0; rr < 4; rr++) {
        int r = warp*4 + rr;
        int n = n0 + r;
        if (n >= NN) continue;
        float v0 = Ls[r*48 + lane];
        float v1 = (lane < NCLS - 32) ? Ls[r*48 + 32 + lane] : -INFINITY;
        float mx = fmaxf(v0, v1);
        #pragma unroll
        for (int off = 16; off > 0; off >>= 1)
            mx = fmaxf(mx, __shfl_xor_sync(0xffffffffu, mx, off));
        float sm = expf(v0 - mx) + ((lane < NCLS - 32) ? expf(v1 - mx) : 0.f);
        #pragma unroll
        for (int off = 16; off > 0; off >>= 1)
            sm += __shfl_xor_sync(0xffffffffu, sm, off);
        float lse = mx + logf(sm);
        out[(size_t)n*NCLS + lane] = v0 - lse;
        if (lane < NCLS - 32) out[(size_t)n*NCLS + 32 + lane] = v1 - lse;
    }
}

// ---------------- host side ----------------
static inline void launch_gemm(const float* A, const float* A2, const float* B,
                               float* C, __half* vh, int M, int Nc, int Kc, int act) {
    dim3 grid((Nc + 127) / 128, (M + 127) / 128);
    sgemm128_k<<<grid, 256>>>(A, A2, B, C, vh, M, Nc, Kc, act);
}

extern "C" void kernel_launch(void* const* d_in, const int* in_sizes, int n_in,
                              void* d_out, int out_size) {
    const float* x     = (const float*)d_in[0];
    const int*   ei    = (const int*)d_in[1];      // int32 (JAX demotes int64)
    const float* w_in  = (const float*)d_in[2];
    const float* w_out = (const float*)d_in[3];
    const float* Wq    = (const float*)d_in[4];
    const float* Wk    = (const float*)d_in[5];
    const float* Wv    = (const float*)d_in[6];
    const float* Wm    = (const float*)d_in[7];
    const float* Wg    = (const float*)d_in[8];
    const float* Wo    = (const float*)d_in[9];
    float* out = (float*)d_out;

    const int* srcA = ei;
    const int* dstA = ei + EE;

    float *h, *h2, *qkvm, *wqkvm, *gagg;
    __half* vh;
    int *cnt, *rowptr, *wptr, *esrc, *bsum, *boff;
    cudaGetSymbolAddress((void**)&h,      g_h);
    cudaGetSymbolAddress((void**)&h2,     g_h2);
    cudaGetSymbolAddress((void**)&qkvm,   g_qkvm);
    cudaGetSymbolAddress((void**)&vh,     g_vh);
    cudaGetSymbolAddress((void**)&wqkvm,  g_wqkvm);
    cudaGetSymbolAddress((void**)&gagg,   g_gagg);
    cudaGetSymbolAddress((void**)&cnt,    g_cnt);
    cudaGetSymbolAddress((void**)&rowptr, g_rowptr);
    cudaGetSymbolAddress((void**)&wptr,   g_wptr);
    cudaGetSymbolAddress((void**)&esrc,   g_esrc);
    cudaGetSymbolAddress((void**)&bsum,   g_bsum);
    cudaGetSymbolAddress((void**)&boff,   g_boff);

    // ---- CSR build (once per call, reused across layers) ----
    zero_cnt_k<<<(NN + 255) / 256, 256>>>(cnt);
    hist_k<<<(EE + 255) / 256, 256>>>(dstA, cnt);
    scan_a_k<<<NB, 1024>>>(cnt, rowptr, bsum);
    scan_b_k<<<1, 32>>>(bsum, boff);
    scan_c_k<<<NB, 1024>>>(cnt, boff, rowptr, wptr);
    scatter_k<<<(EE + 255) / 256, 256>>>(srcA, dstA, wptr, esrc);

    // h = x @ weight_in
    launch_gemm(x, nullptr, w_in, h, nullptr, NN, HID, FIN, 0);

    float* hcur = h;
    float* hnext = h2;

    for (int layer = 0; layer < 2; layer++) {
        const float* wq = Wq + (size_t)layer * HID * (KH*DA);
        const float* wk = Wk + (size_t)layer * HID * (KH*DA);
        const float* wv = Wv + (size_t)layer * HID * (KH*DV);
        const float* wm = Wm + (size_t)layer * HID * DM;
        const float* wg = Wg + (size_t)layer * 320 * KH;
        const float* wo = Wo + (size_t)layer * WO_IN * HID;

        pack_qkvm_k<<<(HID*QSW + 255) / 256, 256>>>(wq, wk, wv, wm, wg, wqkvm);
        launch_gemm(hcur, nullptr, wqkvm, qkvm, vh, NN, QSW, HID, 0);

        node_fused_k<<<(NN + 7) / 8, 256>>>(qkvm, vh, rowptr, esrc, wg, gagg);

        // hnext = leaky_relu([hcur | gagg] @ wo)  — split-A GEMM, K=256
        launch_gemm(hcur, gagg, wo, hnext, nullptr, NN, HID, WO_IN, 1);

        float* t = hcur; hcur = hnext; hnext = t;
    }

    // fused logits + log_softmax (block-tiled)
    logits_lsm2_k<<<(NN + 31) / 32, 256>>>(hcur, w_out, out);
}

// round 16
// speedup vs baseline: 1.1187x; 1.0012x over previous
#include <cuda_runtime.h>
#include <cuda_fp16.h>
#include <math.h>

// ---------------- problem dims (fixed) ----------------
#define NN 50000
#define EE 600000
#define FIN 128
#define HID 128
#define KH 8
#define DA 16
#define DV 16
#define DM 64
#define NCLS 40
#define WO_IN  (HID + KH*DV)       // 256
#define QSW 480                    // GEMM N: q(128)|k(128)|v(128)|m(64)|gx(8)|gm(8)|pad(16)
#define QS32 288                   // fp32 store stride: q(128)|k(128)|gx(8)|pad(24)
#define VSH 256                    // fp16 store stride: v(128)|m(64)|gm(8)|pad
#define SLOPE 0.1f
#define NB 49                      // scan blocks: ceil(NN/1024)

// ---------------- device scratch (no allocations allowed) ----------------
__device__ float  g_h    [NN*HID];
__device__ float  g_h2   [NN*HID];
__device__ float  g_qkvm [(size_t)NN*QS32];
__device__ __half g_vh   [(size_t)NN*VSH];
__device__ float  g_wqkvm[HID*QSW];
__device__ float  g_gagg [NN*HID];
__device__ int    g_cnt   [NN];
__device__ int    g_rowptr[NN+1];
__device__ int    g_wptr  [NN];
__device__ int    g_esrc  [EE];
__device__ int    g_bsum  [64];

// ---------------- f32x2 packed helpers ----------------
__device__ __forceinline__ unsigned long long fma2(unsigned long long a,
                                                   unsigned long long b,
                                                   unsigned long long c) {
    unsigned long long d;
    asm("fma.rn.f32x2 %0, %1, %2, %3;" : "=l"(d) : "l"(a), "l"(b), "l"(c));
    return d;
}
__device__ __forceinline__ unsigned long long dup2(float x) {
    unsigned long long d;
    asm("mov.b64 %0, {%1, %1};" : "=l"(d) : "f"(x));
    return d;
}
__device__ __forceinline__ void unpk2(unsigned long long d, float& lo, float& hi) {
    asm("mov.b64 {%0, %1}, %2;" : "=f"(lo), "=f"(hi) : "l"(d));
}

// ---------------- CSR build ----------------
__global__ void zero_cnt_k(int* cnt) {
    int i = blockIdx.x * blockDim.x + threadIdx.x;
    if (i < NN) cnt[i] = 0;
}
__global__ void hist_k(const int* __restrict__ dst, int* __restrict__ cnt) {
    int e = blockIdx.x * blockDim.x + threadIdx.x;
    if (e < EE) atomicAdd(&cnt[dst[e]], 1);
}
__global__ void scan_a_k(const int* __restrict__ cnt, int* __restrict__ rowptr,
                         int* __restrict__ bsum) {
    __shared__ int sh[1024];
    int t = threadIdx.x;
    int i = blockIdx.x * 1024 + t;
    int v = (i < NN) ? cnt[i] : 0;
    sh[t] = v; __syncthreads();
    #pragma unroll
    for (int off = 1; off < 1024; off <<= 1) {
        int u = (t >= off) ? sh[t - off] : 0;
        __syncthreads();
        sh[t] += u;
        __syncthreads();
    }
    if (i < NN) rowptr[i + 1] = sh[t];
    if (t == 1023) bsum[blockIdx.x] = sh[t];
}
// fixup + wptr; each block computes its own prefix over bsum (scan_b folded in)
__global__ void scan_c_k(const int* __restrict__ cnt, const int* __restrict__ bsum,
                         int* __restrict__ rowptr, int* __restrict__ wptr) {
    __shared__ int pre[64];
    __shared__ int boffs;
    int t = threadIdx.x;
    int b = blockIdx.x;
    if (t < 64) pre[t] = (t < b) ? bsum[t] : 0;
    __syncthreads();
    if (t == 0) {
        int s = 0;
        #pragma unroll
        for (int j = 0; j < 64; j++) s += pre[j];
        boffs = s;
    }
    __syncthreads();
    int boff = boffs;
    int i = b * 1024 + t;
    if (i == 0) rowptr[0] = 0;
    if (i < NN) {
        int e = rowptr[i + 1] + boff;
        rowptr[i + 1] = e;
        wptr[i] = e - cnt[i];
    }
}
__global__ void scatter_k(const int* __restrict__ src, const int* __restrict__ dst,
                          int* __restrict__ wptr, int* __restrict__ esrc) {
    int e = blockIdx.x * blockDim.x + threadIdx.x;
    if (e < EE) {
        int pos = atomicAdd(&wptr[dst[e]], 1);
        esrc[pos] = src[e];
    }
}

// pack layer weights [128 x 480] = [Wq | Wk | Wv | Wm | Wg_x | Wg_mean | 0pad]
__global__ void pack_qkvm_k(const float* __restrict__ Wq, const float* __restrict__ Wk,
                            const float* __restrict__ Wv, const float* __restrict__ Wm,
                            const float* __restrict__ Wg, float* __restrict__ Bf) {
    int idx = blockIdx.x * blockDim.x + threadIdx.x;
    if (idx >= HID*QSW) return;
    int r = idx / QSW, c = idx % QSW;
    float v;
    if      (c < 128) v = Wq[r*128 + c];
    else if (c < 256) v = Wk[r*128 + (c-128)];
    else if (c < 384) v = Wv[r*128 + (c-256)];
    else if (c < 448) v = Wm[r*64  + (c-384)];
    else if (c < 456) v = Wg[r*KH + (c-448)];            // x rows of Wg
    else if (c < 464) v = Wg[(192 + r)*KH + (c-456)];    // mean rows of Wg
    else              v = 0.f;                           // pad
    Bf[idx] = v;
}

// ---------------- 128x128x16 SGEMM, 8x8 microtile, f32x2, double-buffered ----
// A2 != null: split-A, Kc=256; K 0..127 from A, 128..255 from A2 (stride 128).
// vh != null: qkvm mode (Nc=480): fp32 q|k|gx -> C stride QS32; fp16 v|m|gm -> vh.
__global__ __launch_bounds__(256, 2)
void sgemm128_k(const float* __restrict__ A, const float* __restrict__ A2,
                const float* __restrict__ B,
                float* __restrict__ C, __half* __restrict__ vh,
                int M, int Nc, int Kc, int act) {
    __shared__ float As[2][16][128];
    __shared__ float Bs[2][16][128];
    int tid = threadIdx.x;
    int tx = tid & 15, ty = tid >> 4;
    int rowBase = blockIdx.y * 128;
    int colBase = blockIdx.x * 128;

    int arow  = tid >> 1;
    int acol4 = (tid & 1) * 4;
    int brow  = tid >> 5;
    int bcol4 = (tid & 31) * 4;
    int agr = rowBase + arow;
    int bgc = colBase + bcol4;
    int KcA = A2 ? 128 : Kc;

    float4 pa[2], pb[2];

    #pragma unroll
    for (int half = 0; half < 2; half++) {
        int ac = acol4 + half * 8;
        pa[half] = make_float4(0.f, 0.f, 0.f, 0.f);
        if (agr < M) pa[half] = *(const float4*)(A + (size_t)agr*KcA + ac);
        pb[half] = make_float4(0.f, 0.f, 0.f, 0.f);
        if (bgc < Nc) pb[half] = *(const float4*)(B + (size_t)(brow + half*8)*Nc + bgc);
    }
    #pragma unroll
    for (int half = 0; half < 2; half++) {
        int ac = acol4 + half * 8;
        As[0][ac+0][arow] = pa[half].x;
        As[0][ac+1][arow] = pa[half].y;
        As[0][ac+2][arow] = pa[half].z;
        As[0][ac+3][arow] = pa[half].w;
        *(float4*)&Bs[0][brow + half*8][bcol4] = pb[half];
    }
    __syncthreads();

    unsigned long long acc2[8][4];
    #pragma unroll
    for (int i = 0; i < 8; i++)
        #pragma unroll
        for (int j = 0; j < 4; j++) acc2[i][j] = 0ull;

    int nchunks = Kc >> 4;
    for (int c = 0; c < nchunks; c++) {
        int cur = c & 1;
        if (c + 1 < nchunks) {
            int k0 = (c + 1) << 4;
            const float* Ap = A;
            int kk0 = k0;
            if (A2 && k0 >= 128) { Ap = A2; kk0 = k0 - 128; }
            #pragma unroll
            for (int half = 0; half < 2; half++) {
                int ac = acol4 + half * 8;
                pa[half] = make_float4(0.f, 0.f, 0.f, 0.f);
                if (agr < M) pa[half] = *(const float4*)(Ap + (size_t)agr*KcA + kk0 + ac);
                pb[half] = make_float4(0.f, 0.f, 0.f, 0.f);
                if (bgc < Nc) pb[half] = *(const float4*)(B + (size_t)(k0 + brow + half*8)*Nc + bgc);
            }
        }
        #pragma unroll
        for (int kk = 0; kk < 16; kk++) {
            float4 a0 = *(const float4*)&As[cur][kk][ty*4];
            float4 a1 = *(const float4*)&As[cur][kk][64 + ty*4];
            const unsigned long long* bp0 = (const unsigned long long*)&Bs[cur][kk][tx*4];
            const unsigned long long* bp1 = (const unsigned long long*)&Bs[cur][kk][64 + tx*4];
            unsigned long long b2[4] = {bp0[0], bp0[1], bp1[0], bp1[1]};
            float a[8] = {a0.x,a0.y,a0.z,a0.w, a1.x,a1.y,a1.z,a1.w};
            #pragma unroll
            for (int i = 0; i < 8; i++) {
                unsigned long long ad = dup2(a[i]);
                acc2[i][0] = fma2(ad, b2[0], acc2[i][0]);
                acc2[i][1] = fma2(ad, b2[1], acc2[i][1]);
                acc2[i][2] = fma2(ad, b2[2], acc2[i][2]);
                acc2[i][3] = fma2(ad, b2[3], acc2[i][3]);
            }
        }
        if (c + 1 < nchunks) {
            int nxt = cur ^ 1;
            #pragma unroll
            for (int half = 0; half < 2; half++) {
                int ac = acol4 + half * 8;
                As[nxt][ac+0][arow] = pa[half].x;
                As[nxt][ac+1][arow] = pa[half].y;
                As[nxt][ac+2][arow] = pa[half].z;
                As[nxt][ac+3][arow] = pa[half].w;
                *(float4*)&Bs[nxt][brow + half*8][bcol4] = pb[half];
            }
        }
        __syncthreads();
    }

    #pragma unroll
    for (int ih = 0; ih < 2; ih++) {
        #pragma unroll
        for (int i = 0; i < 4; i++) {
            int gr = rowBase + ih*64 + ty*4 + i;
            if (gr >= M) continue;
            #pragma unroll
            for (int jh = 0; jh < 2; jh++) {
                int gc = colBase + jh*64 + tx*4;
                if (gc >= Nc) continue;
                float4 vv;
                unpk2(acc2[ih*4+i][jh*2+0], vv.x, vv.y);
                unpk2(acc2[ih*4+i][jh*2+1], vv.z, vv.w);
                if (vh == nullptr) {
                    if (act == 1) {
                        vv.x = vv.x > 0.f ? vv.x : SLOPE*vv.x;
                        vv.y = vv.y > 0.f ? vv.y : SLOPE*vv.y;
                        vv.z = vv.z > 0.f ? vv.z : SLOPE*vv.z;
                        vv.w = vv.w > 0.f ? vv.w : SLOPE*vv.w;
                    }
                    *(float4*)(C + (size_t)gr*Nc + gc) = vv;
                } else {
                    if (gc < 256) {
                        *(float4*)(C + (size_t)gr*QS32 + gc) = vv;
                    } else if (gc >= 448 && gc < 456) {
                        *(float4*)(C + (size_t)gr*QS32 + 256 + (gc - 448)) = vv;
                    }
                    if (gc >= 256 && gc < 464 && !(gc >= 448 && gc < 456)) {
                        int hidx;
                        if      (gc < 384) hidx = gc - 256;          // v: 0..127
                        else if (gc < 448) hidx = 128 + (gc - 384);  // m: 128..191
                        else               hidx = 192 + (gc - 456);  // gm: 192..199
                        __half2 h0 = __floats2half2_rn(vv.x, vv.y);
                        __half2 h1 = __floats2half2_rn(vv.z, vv.w);
                        uint2 pk;
                        pk.x = *(unsigned int*)&h0;
                        pk.y = *(unsigned int*)&h1;
                        *(uint2*)(vh + (size_t)gr*VSH + hidx) = pk;
                    }
                }
            }
        }
    }
}

// ---------------- fused node kernel: attn+pool+gate -> gagg ----------------
__global__ __launch_bounds__(256)
void node_fused_k(const float* __restrict__ qkvm, const __half* __restrict__ vh,
                  const int* __restrict__ rowptr, const int* __restrict__ esrc,
                  const float* __restrict__ Wg, float* __restrict__ gagg) {
    __shared__ float Ws[DM][KH+1];
    int tid = threadIdx.x;                // 256
    for (int i = tid; i < DM*KH; i += 256) Ws[i/KH][i%KH] = Wg[(128 + i/KH)*KH + (i%KH)];
    __syncthreads();

    int warp = tid >> 5, lane = tid & 31;
    int n = blockIdx.x * 8 + warp;
    if (n >= NN) return;
    int head = lane >> 2;

    float4 q4 = *(const float4*)(qkvm + (size_t)n*QS32 + lane*4);   // q
    int start = rowptr[n], end = rowptr[n+1];
    int cnt = end - start;

    float smx = -INFINITY, denom = 0.f;
    float4 acc = make_float4(0.f, 0.f, 0.f, 0.f);
    float mx0 = -INFINITY, mx1 = -INFINITY;
    float gmsum = 0.f;

    for (int i = start; i < end; i++) {
        int s = esrc[i];
        const float* kb = qkvm + (size_t)s*QS32 + 128;
        float4 k4 = *(const float4*)(kb + lane*4);
        float p = q4.x*k4.x + q4.y*k4.y + q4.z*k4.z + q4.w*k4.w;
        p += __shfl_xor_sync(0xffffffffu, p, 1);
        p += __shfl_xor_sync(0xffffffffu, p, 2);
        float nm = fmaxf(smx, p);
        float sc = __expf(smx - nm), ex = __expf(p - nm);
        denom = denom*sc + ex;
        const __half* vb = vh + (size_t)s*VSH;
        uint2 raw = *(const uint2*)(vb + lane*4);
        float2 va = __half22float2(*(__half2*)&raw.x);
        float2 vbp = __half22float2(*(__half2*)&raw.y);
        acc.x = acc.x*sc + ex*va.x;
        acc.y = acc.y*sc + ex*va.y;
        acc.z = acc.z*sc + ex*vbp.x;
        acc.w = acc.w*sc + ex*vbp.y;
        smx = nm;
        mx0 = fmaxf(mx0, __half2float(vb[128 + lane]));
        mx1 = fmaxf(mx1, __half2float(vb[160 + lane]));
        gmsum += __half2float(vb[192 + head]);
    }

    float inv = 1.f / (denom + 1e-16f);
    float4 o = make_float4(acc.x*inv, acc.y*inv, acc.z*inv, acc.w*inv);  // agg

    float mp0 = cnt ? mx0 : 0.f, mp1 = cnt ? mx1 : 0.f;
    float invd = 1.f / fmaxf((float)cnt, 1.f);

    float ga[KH] = {};
    #pragma unroll
    for (int oo = 0; oo < KH; oo++)
        ga[oo] = mp0 * Ws[lane][oo] + mp1 * Ws[lane + 32][oo];
    #pragma unroll
    for (int oo = 0; oo < KH; oo++)
        #pragma unroll
        for (int off = 16; off; off >>= 1)
            ga[oo] += __shfl_xor_sync(0xffffffffu, ga[oo], off);

    float gsum = ga[0];
    #pragma unroll
    for (int oo = 1; oo < KH; oo++) if (head == oo) gsum = ga[oo];
    gsum += qkvm[(size_t)n*QS32 + 256 + head];   // x part of gate (fp32)
    gsum += gmsum * invd;                        // mean part of gate
    float gh = 1.f / (1.f + expf(-gsum));

    *(float4*)(gagg + (size_t)n*HID + lane*4) =
        make_float4(gh*o.x, gh*o.y, gh*o.z, gh*o.w);
}

// ---------------- fused logits + log_softmax: block-tiled GEMM ----------------
__global__ __launch_bounds__(256)
void logits_lsm2_k(const float* __restrict__ h, const float* __restrict__ w_out,
                   float* __restrict__ out) {
    __shared__ float Ws[HID][48];
    __shared__ float HsT[HID][33];
    int tid = threadIdx.x;               // 256
    int n0 = blockIdx.x * 32;

    for (int i = tid; i < HID*48; i += 256) {
        int r = i / 48, c = i % 48;
        Ws[r][c] = (c < NCLS) ? w_out[r*NCLS + c] : 0.f;
    }
    for (int idx = tid; idx < 32*32; idx += 256) {
        int r = idx >> 5, c4 = (idx & 31) * 4;
        int n = n0 + r;
        float4 hv = *(const float4*)(h + (size_t)((n < NN) ? n : 0)*HID + c4);
        HsT[c4+0][r] = hv.x;
        HsT[c4+1][r] = hv.y;
        HsT[c4+2][r] = hv.z;
        HsT[c4+3][r] = hv.w;
    }
    __syncthreads();

    int tx = tid & 15, ty = tid >> 4;
    float acc[2][3] = {};
    #pragma unroll 4
    for (int kk = 0; kk < HID; kk++) {
        float a0 = HsT[kk][ty*2 + 0];
        float a1 = HsT[kk][ty*2 + 1];
        float b0 = Ws[kk][tx*3 + 0];
        float b1 = Ws[kk][tx*3 + 1];
        float b2 = Ws[kk][tx*3 + 2];
        acc[0][0] += a0*b0; acc[0][1] += a0*b1; acc[0][2] += a0*b2;
        acc[1][0] += a1*b0; acc[1][1] += a1*b1; acc[1][2] += a1*b2;
    }
    __syncthreads();

    float* Ls = &HsT[0][0];
    #pragma unroll
    for (int i = 0; i < 2; i++)
        #pragma unroll
        for (int j = 0; j < 3; j++)
            Ls[(ty*2 + i)*48 + tx*3 + j] = acc[i][j];
    __syncthreads();

    int warp = tid >> 5, lane = tid & 31;
    #pragma unroll
    for (int rr = 0; rr < 4; rr++) {
        int r = warp*4 + rr;
        int n = n0 + r;
        if (n >= NN) continue;
        float v0 = Ls[r*48 + lane];
        float v1 = (lane < NCLS - 32) ? Ls[r*48 + 32 + lane] : -INFINITY;
        float mx = fmaxf(v0, v1);
        #pragma unroll
        for (int off = 16; off > 0; off >>= 1)
            mx = fmaxf(mx, __shfl_xor_sync(0xffffffffu, mx, off));
        float sm = expf(v0 - mx) + ((lane < NCLS - 32) ? expf(v1 - mx) : 0.f);
        #pragma unroll
        for (int off = 16; off > 0; off >>= 1)
            sm += __shfl_xor_sync(0xffffffffu, sm, off);
        float lse = mx + logf(sm);
        out[(size_t)n*NCLS + lane] = v0 - lse;
        if (lane < NCLS - 32) out[(size_t)n*NCLS + 32 + lane] = v1 - lse;
    }
}

// ---------------- host side ----------------
static inline void launch_gemm(const float* A, const float* A2, const float* B,
                               float* C, __half* vh, int M, int Nc, int Kc, int act) {
    dim3 grid((Nc + 127) / 128, (M + 127) / 128);
    sgemm128_k<<<grid, 256>>>(A, A2, B, C, vh, M, Nc, Kc, act);
}

extern "C" void kernel_launch(void* const* d_in, const int* in_sizes, int n_in,
                              void* d_out, int out_size) {
    const float* x     = (const float*)d_in[0];
    const int*   ei    = (const int*)d_in[1];      // int32 (JAX demotes int64)
    const float* w_in  = (const float*)d_in[2];
    const float* w_out = (const float*)d_in[3];
    const float* Wq    = (const float*)d_in[4];
    const float* Wk    = (const float*)d_in[5];
    const float* Wv    = (const float*)d_in[6];
    const float* Wm    = (const float*)d_in[7];
    const float* Wg    = (const float*)d_in[8];
    const float* Wo    = (const float*)d_in[9];
    float* out = (float*)d_out;

    const int* srcA = ei;
    const int* dstA = ei + EE;

    float *h, *h2, *qkvm, *wqkvm, *gagg;
    __half* vh;
    int *cnt, *rowptr, *wptr, *esrc, *bsum;
    cudaGetSymbolAddress((void**)&h,      g_h);
    cudaGetSymbolAddress((void**)&h2,     g_h2);
    cudaGetSymbolAddress((void**)&qkvm,   g_qkvm);
    cudaGetSymbolAddress((void**)&vh,     g_vh);
    cudaGetSymbolAddress((void**)&wqkvm,  g_wqkvm);
    cudaGetSymbolAddress((void**)&gagg,   g_gagg);
    cudaGetSymbolAddress((void**)&cnt,    g_cnt);
    cudaGetSymbolAddress((void**)&rowptr, g_rowptr);
    cudaGetSymbolAddress((void**)&wptr,   g_wptr);
    cudaGetSymbolAddress((void**)&esrc,   g_esrc);
    cudaGetSymbolAddress((void**)&bsum,   g_bsum);

    // Launch order arranged so launch #6 is the LAYER-0 QKVM GEMM (ncu -s 5 -c 1
    // profiles the 6th launch — we finally get the big GEMM's roofline).
    // (1) input GEMM: h = x @ w_in
    launch_gemm(x, nullptr, w_in, h, nullptr, NN, HID, FIN, 0);
    // (2) pack layer-0 weights
    pack_qkvm_k<<<(HID*QSW + 255) / 256, 256>>>(Wq, Wk, Wv, Wm, Wg, wqkvm);
    // (3..5) CSR build head
    zero_cnt_k<<<(NN + 255) / 256, 256>>>(cnt);
    hist_k<<<(EE + 255) / 256, 256>>>(dstA, cnt);
    scan_a_k<<<NB, 1024>>>(cnt, rowptr, bsum);
    // (6) layer-0 qkvm GEMM  <-- PROFILED LAUNCH
    launch_gemm(h, nullptr, wqkvm, qkvm, vh, NN, QSW, HID, 0);
    // (7..8) CSR build tail (scan_b folded into scan_c)
    scan_c_k<<<NB, 1024>>>(cnt, bsum, rowptr, wptr);
    scatter_k<<<(EE + 255) / 256, 256>>>(srcA, dstA, wptr, esrc);

    float* hcur = h;
    float* hnext = h2;

    // ---- layer 0 (qkvm GEMM already issued above) ----
    node_fused_k<<<(NN + 7) / 8, 256>>>(qkvm, vh, rowptr, esrc, Wg, gagg);
    launch_gemm(hcur, gagg, Wo, hnext, nullptr, NN, HID, WO_IN, 1);
    { float* t = hcur; hcur = hnext; hnext = t; }

    // ---- layer 1 ----
    {
        const float* wq = Wq + (size_t)HID * (KH*DA);
        const float* wk = Wk + (size_t)HID * (KH*DA);
        const float* wv = Wv + (size_t)HID * (KH*DV);
        const float* wm = Wm + (size_t)HID * DM;
        const float* wg = Wg + (size_t)320 * KH;
        const float* wo = Wo + (size_t)WO_IN * HID;

        pack_qkvm_k<<<(HID*QSW + 255) / 256, 256>>>(wq, wk, wv, wm, wg, wqkvm);
        launch_gemm(hcur, nullptr, wqkvm, qkvm, vh, NN, QSW, HID, 0);
        node_fused_k<<<(NN + 7) / 8, 256>>>(qkvm, vh, rowptr, esrc, wg, gagg);
        launch_gemm(hcur, gagg, wo, hnext, nullptr, NN, HID, WO_IN, 1);
        float* t = hcur; hcur = hnext; hnext = t;
    }

    // fused logits + log_softmax (block-tiled)
    logits_lsm2_k<<<(NN + 31) / 32, 256>>>(hcur, w_out, out);
}

// round 17
// speedup vs baseline: 1.1253x; 1.0059x over previous
#include <cuda_runtime.h>
#include <cuda_fp16.h>
#include <math.h>

// ---------------- problem dims (fixed) ----------------
#define NN 50000
#define EE 600000
#define FIN 128
#define HID 128
#define KH 8
#define DA 16
#define DV 16
#define DM 64
#define NCLS 40
#define WO_IN  (HID + KH*DV)       // 256
#define QSW 480                    // GEMM N: q(128)|k(128)|v(128)|m(64)|gx(8)|gm(8)|pad(16)
#define QS32 288                   // fp32 store stride: q(128)|k(128)|gx(8)|pad(24)
#define VSH 256                    // fp16 store stride: v(128)|m(64)|gm(8)|pad
#define SLOPE 0.1f
#define NB 49                      // scan blocks: ceil(NN/1024)

// ---------------- device scratch (no allocations allowed) ----------------
__device__ float  g_h    [NN*HID];
__device__ float  g_h2   [NN*HID];
__device__ float  g_qkvm [(size_t)NN*QS32];
__device__ __half g_vh   [(size_t)NN*VSH];
__device__ float  g_wqkvm[2][HID*QSW];     // both layers packed upfront
__device__ float  g_gagg [NN*HID];
__device__ int    g_cnt   [NN];
__device__ int    g_rowptr[NN+1];
__device__ int    g_wptr  [NN];
__device__ int    g_esrc  [EE];
__device__ int    g_bsum  [64];

// ---------------- f32x2 packed helpers ----------------
__device__ __forceinline__ unsigned long long fma2(unsigned long long a,
                                                   unsigned long long b,
                                                   unsigned long long c) {
    unsigned long long d;
    asm("fma.rn.f32x2 %0, %1, %2, %3;" : "=l"(d) : "l"(a), "l"(b), "l"(c));
    return d;
}
__device__ __forceinline__ unsigned long long dup2(float x) {
    unsigned long long d;
    asm("mov.b64 %0, {%1, %1};" : "=l"(d) : "f"(x));
    return d;
}
__device__ __forceinline__ void unpk2(unsigned long long d, float& lo, float& hi) {
    asm("mov.b64 {%0, %1}, %2;" : "=f"(lo), "=f"(hi) : "l"(d));
}

// ---------------- CSR build ----------------
__global__ void zero_cnt_k(int* cnt) {
    int i = blockIdx.x * blockDim.x + threadIdx.x;
    if (i < NN) cnt[i] = 0;
}
__global__ void hist_k(const int* __restrict__ dst, int* __restrict__ cnt) {
    int e = blockIdx.x * blockDim.x + threadIdx.x;
    if (e < EE) atomicAdd(&cnt[dst[e]], 1);
}
__global__ void scan_a_k(const int* __restrict__ cnt, int* __restrict__ rowptr,
                         int* __restrict__ bsum) {
    __shared__ int sh[1024];
    int t = threadIdx.x;
    int i = blockIdx.x * 1024 + t;
    int v = (i < NN) ? cnt[i] : 0;
    sh[t] = v; __syncthreads();
    #pragma unroll
    for (int off = 1; off < 1024; off <<= 1) {
        int u = (t >= off) ? sh[t - off] : 0;
        __syncthreads();
        sh[t] += u;
        __syncthreads();
    }
    if (i < NN) rowptr[i + 1] = sh[t];
    if (t == 1023) bsum[blockIdx.x] = sh[t];
}
// fixup + wptr; each block computes its own prefix over bsum
__global__ void scan_c_k(const int* __restrict__ cnt, const int* __restrict__ bsum,
                         int* __restrict__ rowptr, int* __restrict__ wptr) {
    __shared__ int pre[64];
    __shared__ int boffs;
    int t = threadIdx.x;
    int b = blockIdx.x;
    if (t < 64) pre[t] = (t < b) ? bsum[t] : 0;
    __syncthreads();
    if (t == 0) {
        int s = 0;
        #pragma unroll
        for (int j = 0; j < 64; j++) s += pre[j];
        boffs = s;
    }
    __syncthreads();
    int boff = boffs;
    int i = b * 1024 + t;
    if (i == 0) rowptr[0] = 0;
    if (i < NN) {
        int e = rowptr[i + 1] + boff;
        rowptr[i + 1] = e;
        wptr[i] = e - cnt[i];
    }
}
__global__ void scatter_k(const int* __restrict__ src, const int* __restrict__ dst,
                          int* __restrict__ wptr, int* __restrict__ esrc) {
    int e = blockIdx.x * blockDim.x + threadIdx.x;
    if (e < EE) {
        int pos = atomicAdd(&wptr[dst[e]], 1);
        esrc[pos] = src[e];
    }
}

// pack BOTH layers' weights [2][128 x 480]
__global__ void pack_qkvm2_k(const float* __restrict__ Wq, const float* __restrict__ Wk,
                             const float* __restrict__ Wv, const float* __restrict__ Wm,
                             const float* __restrict__ Wg, float* __restrict__ Bf) {
    int idx = blockIdx.x * blockDim.x + threadIdx.x;
    if (idx >= 2*HID*QSW) return;
    int layer = idx / (HID*QSW);
    int rem = idx - layer*(HID*QSW);
    int r = rem / QSW, c = rem % QSW;
    const float* wq = Wq + (size_t)layer * HID * (KH*DA);
    const float* wk = Wk + (size_t)layer * HID * (KH*DA);
    const float* wv = Wv + (size_t)layer * HID * (KH*DV);
    const float* wm = Wm + (size_t)layer * HID * DM;
    const float* wg = Wg + (size_t)layer * 320 * KH;
    float v;
    if      (c < 128) v = wq[r*128 + c];
    else if (c < 256) v = wk[r*128 + (c-128)];
    else if (c < 384) v = wv[r*128 + (c-256)];
    else if (c < 448) v = wm[r*64  + (c-384)];
    else if (c < 456) v = wg[r*KH + (c-448)];            // x rows of Wg
    else if (c < 464) v = wg[(192 + r)*KH + (c-456)];    // mean rows of Wg
    else              v = 0.f;                           // pad
    Bf[idx] = v;
}

// ---------------- 128x128x16 SGEMM, 8x8 microtile, f32x2, double-buffered ----
// A2 != null: split-A, Kc=256; K 0..127 from A, 128..255 from A2 (stride 128).
// vh != null: qkvm mode (Nc=480): fp32 q|k|gx -> C stride QS32; fp16 v|m|gm -> vh.
__global__ __launch_bounds__(256, 2)
void sgemm128_k(const float* __restrict__ A, const float* __restrict__ A2,
                const float* __restrict__ B,
                float* __restrict__ C, __half* __restrict__ vh,
                int M, int Nc, int Kc, int act) {
    __shared__ float As[2][16][128];
    __shared__ float Bs[2][16][128];
    int tid = threadIdx.x;
    int tx = tid & 15, ty = tid >> 4;
    int rowBase = blockIdx.y * 128;
    int colBase = blockIdx.x * 128;

    int arow  = tid >> 1;
    int acol4 = (tid & 1) * 4;
    int brow  = tid >> 5;
    int bcol4 = (tid & 31) * 4;
    int agr = rowBase + arow;
    int bgc = colBase + bcol4;
    int KcA = A2 ? 128 : Kc;

    float4 pa[2], pb[2];

    #pragma unroll
    for (int half = 0; half < 2; half++) {
        int ac = acol4 + half * 8;
        pa[half] = make_float4(0.f, 0.f, 0.f, 0.f);
        if (agr < M) pa[half] = *(const float4*)(A + (size_t)agr*KcA + ac);
        pb[half] = make_float4(0.f, 0.f, 0.f, 0.f);
        if (bgc < Nc) pb[half] = *(const float4*)(B + (size_t)(brow + half*8)*Nc + bgc);
    }
    #pragma unroll
    for (int half = 0; half < 2; half++) {
        int ac = acol4 + half * 8;
        As[0][ac+0][arow] = pa[half].x;
        As[0][ac+1][arow] = pa[half].y;
        As[0][ac+2][arow] = pa[half].z;
        As[0][ac+3][arow] = pa[half].w;
        *(float4*)&Bs[0][brow + half*8][bcol4] = pb[half];
    }
    __syncthreads();

    unsigned long long acc2[8][4];
    #pragma unroll
    for (int i = 0; i < 8; i++)
        #pragma unroll
        for (int j = 0; j < 4; j++) acc2[i][j] = 0ull;

    int nchunks = Kc >> 4;
    for (int c = 0; c < nchunks; c++) {
        int cur = c & 1;
        if (c + 1 < nchunks) {
            int k0 = (c + 1) << 4;
            const float* Ap = A;
            int kk0 = k0;
            if (A2 && k0 >= 128) { Ap = A2; kk0 = k0 - 128; }
            #pragma unroll
            for (int half = 0; half < 2; half++) {
                int ac = acol4 + half * 8;
                pa[half] = make_float4(0.f, 0.f, 0.f, 0.f);
                if (agr < M) pa[half] = *(const float4*)(Ap + (size_t)agr*KcA + kk0 + ac);
                pb[half] = make_float4(0.f, 0.f, 0.f, 0.f);
                if (bgc < Nc) pb[half] = *(const float4*)(B + (size_t)(k0 + brow + half*8)*Nc + bgc);
            }
        }
        #pragma unroll
        for (int kk = 0; kk < 16; kk++) {
            float4 a0 = *(const float4*)&As[cur][kk][ty*4];
            float4 a1 = *(const float4*)&As[cur][kk][64 + ty*4];
            const unsigned long long* bp0 = (const unsigned long long*)&Bs[cur][kk][tx*4];
            const unsigned long long* bp1 = (const unsigned long long*)&Bs[cur][kk][64 + tx*4];
            unsigned long long b2[4] = {bp0[0], bp0[1], bp1[0], bp1[1]};
            float a[8] = {a0.x,a0.y,a0.z,a0.w, a1.x,a1.y,a1.z,a1.w};
            #pragma unroll
            for (int i = 0; i < 8; i++) {
                unsigned long long ad = dup2(a[i]);
                acc2[i][0] = fma2(ad, b2[0], acc2[i][0]);
                acc2[i][1] = fma2(ad, b2[1], acc2[i][1]);
                acc2[i][2] = fma2(ad, b2[2], acc2[i][2]);
                acc2[i][3] = fma2(ad, b2[3], acc2[i][3]);
            }
        }
        if (c + 1 < nchunks) {
            int nxt = cur ^ 1;
            #pragma unroll
            for (int half = 0; half < 2; half++) {
                int ac = acol4 + half * 8;
                As[nxt][ac+0][arow] = pa[half].x;
                As[nxt][ac+1][arow] = pa[half].y;
                As[nxt][ac+2][arow] = pa[half].z;
                As[nxt][ac+3][arow] = pa[half].w;
                *(float4*)&Bs[nxt][brow + half*8][bcol4] = pb[half];
            }
        }
        __syncthreads();
    }

    #pragma unroll
    for (int ih = 0; ih < 2; ih++) {
        #pragma unroll
        for (int i = 0; i < 4; i++) {
            int gr = rowBase + ih*64 + ty*4 + i;
            if (gr >= M) continue;
            #pragma unroll
            for (int jh = 0; jh < 2; jh++) {
                int gc = colBase + jh*64 + tx*4;
                if (gc >= Nc) continue;
                float4 vv;
                unpk2(acc2[ih*4+i][jh*2+0], vv.x, vv.y);
                unpk2(acc2[ih*4+i][jh*2+1], vv.z, vv.w);
                if (vh == nullptr) {
                    if (act == 1) {
                        vv.x = vv.x > 0.f ? vv.x : SLOPE*vv.x;
                        vv.y = vv.y > 0.f ? vv.y : SLOPE*vv.y;
                        vv.z = vv.z > 0.f ? vv.z : SLOPE*vv.z;
                        vv.w = vv.w > 0.f ? vv.w : SLOPE*vv.w;
                    }
                    *(float4*)(C + (size_t)gr*Nc + gc) = vv;
                } else {
                    if (gc < 256) {
                        *(float4*)(C + (size_t)gr*QS32 + gc) = vv;
                    } else if (gc >= 448 && gc < 456) {
                        *(float4*)(C + (size_t)gr*QS32 + 256 + (gc - 448)) = vv;
                    }
                    if (gc >= 256 && gc < 464 && !(gc >= 448 && gc < 456)) {
                        int hidx;
                        if      (gc < 384) hidx = gc - 256;          // v: 0..127
                        else if (gc < 448) hidx = 128 + (gc - 384);  // m: 128..191
                        else               hidx = 192 + (gc - 456);  // gm: 192..199
                        __half2 h0 = __floats2half2_rn(vv.x, vv.y);
                        __half2 h1 = __floats2half2_rn(vv.z, vv.w);
                        uint2 pk;
                        pk.x = *(unsigned int*)&h0;
                        pk.y = *(unsigned int*)&h1;
                        *(uint2*)(vh + (size_t)gr*VSH + hidx) = pk;
                    }
                }
            }
        }
    }
}

// ---------------- fused node kernel: attn+pool+gate -> gagg ----------------
__global__ __launch_bounds__(256)
void node_fused_k(const float* __restrict__ qkvm, const __half* __restrict__ vh,
                  const int* __restrict__ rowptr, const int* __restrict__ esrc,
                  const float* __restrict__ Wg, float* __restrict__ gagg) {
    __shared__ float Ws[DM][KH+1];
    int tid = threadIdx.x;                // 256
    for (int i = tid; i < DM*KH; i += 256) Ws[i/KH][i%KH] = Wg[(128 + i/KH)*KH + (i%KH)];
    __syncthreads();

    int warp = tid >> 5, lane = tid & 31;
    int n = blockIdx.x * 8 + warp;
    if (n >= NN) return;
    int head = lane >> 2;

    float4 q4 = *(const float4*)(qkvm + (size_t)n*QS32 + lane*4);   // q
    int start = rowptr[n], end = rowptr[n+1];
    int cnt = end - start;

    float smx = -INFINITY, denom = 0.f;
    float4 acc = make_float4(0.f, 0.f, 0.f, 0.f);
    float mx0 = -INFINITY, mx1 = -INFINITY;
    float gmsum = 0.f;

    for (int i = start; i < end; i++) {
        int s = esrc[i];
        const float* kb = qkvm + (size_t)s*QS32 + 128;
        float4 k4 = *(const float4*)(kb + lane*4);
        float p = q4.x*k4.x + q4.y*k4.y + q4.z*k4.z + q4.w*k4.w;
        p += __shfl_xor_sync(0xffffffffu, p, 1);
        p += __shfl_xor_sync(0xffffffffu, p, 2);
        float nm = fmaxf(smx, p);
        float sc = __expf(smx - nm), ex = __expf(p - nm);
        denom = denom*sc + ex;
        const __half* vb = vh + (size_t)s*VSH;
        uint2 raw = *(const uint2*)(vb + lane*4);
        float2 va = __half22float2(*(__half2*)&raw.x);
        float2 vbp = __half22float2(*(__half2*)&raw.y);
        acc.x = acc.x*sc + ex*va.x;
        acc.y = acc.y*sc + ex*va.y;
        acc.z = acc.z*sc + ex*vbp.x;
        acc.w = acc.w*sc + ex*vbp.y;
        smx = nm;
        mx0 = fmaxf(mx0, __half2float(vb[128 + lane]));
        mx1 = fmaxf(mx1, __half2float(vb[160 + lane]));
        gmsum += __half2float(vb[192 + head]);
    }

    float inv = 1.f / (denom + 1e-16f);
    float4 o = make_float4(acc.x*inv, acc.y*inv, acc.z*inv, acc.w*inv);  // agg

    float mp0 = cnt ? mx0 : 0.f, mp1 = cnt ? mx1 : 0.f;
    float invd = 1.f / fmaxf((float)cnt, 1.f);

    float ga[KH] = {};
    #pragma unroll
    for (int oo = 0; oo < KH; oo++)
        ga[oo] = mp0 * Ws[lane][oo] + mp1 * Ws[lane + 32][oo];
    #pragma unroll
    for (int oo = 0; oo < KH; oo++)
        #pragma unroll
        for (int off = 16; off; off >>= 1)
            ga[oo] += __shfl_xor_sync(0xffffffffu, ga[oo], off);

    float gsum = ga[0];
    #pragma unroll
    for (int oo = 1; oo < KH; oo++) if (head == oo) gsum = ga[oo];
    gsum += qkvm[(size_t)n*QS32 + 256 + head];   // x part of gate (fp32)
    gsum += gmsum * invd;                        // mean part of gate
    float gh = 1.f / (1.f + expf(-gsum));

    *(float4*)(gagg + (size_t)n*HID + lane*4) =
        make_float4(gh*o.x, gh*o.y, gh*o.z, gh*o.w);
}

// ---------------- fused logits + log_softmax: block-tiled GEMM ----------------
__global__ __launch_bounds__(256)
void logits_lsm2_k(const float* __restrict__ h, const float* __restrict__ w_out,
                   float* __restrict__ out) {
    __shared__ float Ws[HID][48];
    __shared__ float HsT[HID][33];
    int tid = threadIdx.x;               // 256
    int n0 = blockIdx.x * 32;

    for (int i = tid; i < HID*48; i += 256) {
        int r = i / 48, c = i % 48;
        Ws[r][c] = (c < NCLS) ? w_out[r*NCLS + c] : 0.f;
    }
    for (int idx = tid; idx < 32*32; idx += 256) {
        int r = idx >> 5, c4 = (idx & 31) * 4;
        int n = n0 + r;
        float4 hv = *(const float4*)(h + (size_t)((n < NN) ? n : 0)*HID + c4);
        HsT[c4+0][r] = hv.x;
        HsT[c4+1][r] = hv.y;
        HsT[c4+2][r] = hv.z;
        HsT[c4+3][r] = hv.w;
    }
    __syncthreads();

    int tx = tid & 15, ty = tid >> 4;
    float acc[2][3] = {};
    #pragma unroll 4
    for (int kk = 0; kk < HID; kk++) {
        float a0 = HsT[kk][ty*2 + 0];
        float a1 = HsT[kk][ty*2 + 1];
        float b0 = Ws[kk][tx*3 + 0];
        float b1 = Ws[kk][tx*3 + 1];
        float b2 = Ws[kk][tx*3 + 2];
        acc[0][0] += a0*b0; acc[0][1] += a0*b1; acc[0][2] += a0*b2;
        acc[1][0] += a1*b0; acc[1][1] += a1*b1; acc[1][2] += a1*b2;
    }
    __syncthreads();

    float* Ls = &HsT[0][0];
    #pragma unroll
    for (int i = 0; i < 2; i++)
        #pragma unroll
        for (int j = 0; j < 3; j++)
            Ls[(ty*2 + i)*48 + tx*3 + j] = acc[i][j];
    __syncthreads();

    int warp = tid >> 5, lane = tid & 31;
    #pragma unroll
    for (int rr = 0; rr < 4; rr++) {
        int r = warp*4 + rr;
        int n = n0 + r;
        if (n >= NN) continue;
        float v0 = Ls[r*48 + lane];
        float v1 = (lane < NCLS - 32) ? Ls[r*48 + 32 + lane] : -INFINITY;
        float mx = fmaxf(v0, v1);
        #pragma unroll
        for (int off = 16; off > 0; off >>= 1)
            mx = fmaxf(mx, __shfl_xor_sync(0xffffffffu, mx, off));
        float sm = expf(v0 - mx) + ((lane < NCLS - 32) ? expf(v1 - mx) : 0.f);
        #pragma unroll
        for (int off = 16; off > 0; off >>= 1)
            sm += __shfl_xor_sync(0xffffffffu, sm, off);
        float lse = mx + logf(sm);
        out[(size_t)n*NCLS + lane] = v0 - lse;
        if (lane < NCLS - 32) out[(size_t)n*NCLS + 32 + lane] = v1 - lse;
    }
}

// ---------------- host side ----------------
static inline void launch_gemm(const float* A, const float* A2, const float* B,
                               float* C, __half* vh, int M, int Nc, int Kc, int act) {
    dim3 grid((Nc + 127) / 128, (M + 127) / 128);
    sgemm128_k<<<grid, 256>>>(A, A2, B, C, vh, M, Nc, Kc, act);
}

extern "C" void kernel_launch(void* const* d_in, const int* in_sizes, int n_in,
                              void* d_out, int out_size) {
    const float* x     = (const float*)d_in[0];
    const int*   ei    = (const int*)d_in[1];      // int32 (JAX demotes int64)
    const float* w_in  = (const float*)d_in[2];
    const float* w_out = (const float*)d_in[3];
    const float* Wq    = (const float*)d_in[4];
    const float* Wk    = (const float*)d_in[5];
    const float* Wv    = (const float*)d_in[6];
    const float* Wm    = (const float*)d_in[7];
    const float* Wg    = (const float*)d_in[8];
    const float* Wo    = (const float*)d_in[9];
    float* out = (float*)d_out;

    const int* srcA = ei;
    const int* dstA = ei + EE;

    float *h, *h2, *qkvm, *wqkvm, *gagg;
    __half* vh;
    int *cnt, *rowptr, *wptr, *esrc, *bsum;
    cudaGetSymbolAddress((void**)&h,      g_h);
    cudaGetSymbolAddress((void**)&h2,     g_h2);
    cudaGetSymbolAddress((void**)&qkvm,   g_qkvm);
    cudaGetSymbolAddress((void**)&vh,     g_vh);
    cudaGetSymbolAddress((void**)&wqkvm,  g_wqkvm);
    cudaGetSymbolAddress((void**)&gagg,   g_gagg);
    cudaGetSymbolAddress((void**)&cnt,    g_cnt);
    cudaGetSymbolAddress((void**)&rowptr, g_rowptr);
    cudaGetSymbolAddress((void**)&wptr,   g_wptr);
    cudaGetSymbolAddress((void**)&esrc,   g_esrc);
    cudaGetSymbolAddress((void**)&bsum,   g_bsum);

    // Harness issues ~2 internal launches first; ncu (-s 5 -c 1) profiles OUR
    // launch #4. Order arranged so #4 = layer-0 qkvm GEMM.
    // (1) input GEMM
    launch_gemm(x, nullptr, w_in, h, nullptr, NN, HID, FIN, 0);
    // (2) pack BOTH layers' weights
    pack_qkvm2_k<<<(2*HID*QSW + 255) / 256, 256>>>(Wq, Wk, Wv, Wm, Wg, wqkvm);
    // (3) zero counters
    zero_cnt_k<<<(NN + 255) / 256, 256>>>(cnt);
    // (4) layer-0 qkvm GEMM   <-- PROFILED LAUNCH
    launch_gemm(h, nullptr, wqkvm, qkvm, vh, NN, QSW, HID, 0);
    // (5..8) CSR build
    hist_k<<<(EE + 255) / 256, 256>>>(dstA, cnt);
    scan_a_k<<<NB, 1024>>>(cnt, rowptr, bsum);
    scan_c_k<<<NB, 1024>>>(cnt, bsum, rowptr, wptr);
    scatter_k<<<(EE + 255) / 256, 256>>>(srcA, dstA, wptr, esrc);

    float* hcur = h;
    float* hnext = h2;

    // ---- layer 0 (qkvm GEMM already issued above) ----
    node_fused_k<<<(NN + 7) / 8, 256>>>(qkvm, vh, rowptr, esrc, Wg, gagg);
    launch_gemm(hcur, gagg, Wo, hnext, nullptr, NN, HID, WO_IN, 1);
    { float* t = hcur; hcur = hnext; hnext = t; }

    // ---- layer 1 ----
    {
        const float* wg = Wg + (size_t)320 * KH;
        const float* wo = Wo + (size_t)WO_IN * HID;
        launch_gemm(hcur, nullptr, wqkvm + HID*QSW, qkvm, vh, NN, QSW, HID, 0);
        node_fused_k<<<(NN + 7) / 8, 256>>>(qkvm, vh, rowptr, esrc, wg, gagg);
        launch_gemm(hcur, gagg, wo, hnext, nullptr, NN, HID, WO_IN, 1);
        float* t = hcur; hcur = hnext; hnext = t;
    }

    // fused logits + log_softmax (block-tiled)
    logits_lsm2_k<<<(NN + 31) / 32, 256>>>(hcur, w_out, out);
}